// round 15
// baseline (speedup 1.0000x reference)
#include <cuda_runtime.h>
#include <cuda_fp16.h>
#include <math.h>
#include <stdint.h>

#define BB 4
#define LL 4096
#define HIDN 1024
#define HH 16
#define DD 64
#define DMM 128
#define CSZ 64
#define NCH 64
#define MM (BB*LL)
#define EPSF 1e-6f
#define NPROC ((size_t)BB*HH*LL*DD)
#define NGATE ((size_t)BB*HH*LL)

static __device__ float g_qkv [(size_t)3*MM*HIDN];
static __device__ float g_proc[(size_t)3*NPROC];
static __device__ float g_gate[(size_t)3*NGATE];
static __device__ float g_wt  [(size_t)64*64*132];
static __device__ __half g_Xhi[(size_t)MM*HIDN];
static __device__ __half g_Whi[(size_t)3*HIDN*HIDN];

__device__ __forceinline__ float sigmf(float x){ return __fdividef(1.0f, 1.0f + __expf(-x)); }

typedef unsigned long long ull;
#define FMA2(acc,a,b) asm("fma.rn.f32x2 %0,%1,%2,%0;" : "+l"(acc) : "l"(a), "l"(b))
__device__ __forceinline__ ull dup2(float a){ ull r; asm("mov.b64 %0,{%1,%1};" : "=l"(r) : "r"(__float_as_uint(a))); return r; }
__device__ __forceinline__ float2 unp(ull v){ uint32_t l,h; asm("mov.b64 {%0,%1},%2;" : "=r"(l),"=r"(h) : "l"(v)); return make_float2(__uint_as_float(l),__uint_as_float(h)); }
__device__ __forceinline__ uint32_t smem_u32(const void* p){
    uint32_t a; asm("{ .reg .u64 t; cvta.to.shared.u64 t, %1; cvt.u32.u64 %0, t; }" : "=r"(a) : "l"(p)); return a;
}
__device__ __forceinline__ float ld_peer(uint32_t laddr, uint32_t prank){
    uint32_t ra; float v;
    asm("mapa.shared::cluster.u32 %0,%1,%2;" : "=r"(ra) : "r"(laddr), "r"(prank));
    asm volatile("ld.shared::cluster.f32 %0,[%1];" : "=f"(v) : "r"(ra));
    return v;
}
__device__ __forceinline__ void ldsm4(uint32_t* r, uint32_t a){
    asm volatile("ldmatrix.sync.aligned.m8n8.x4.shared.b16 {%0,%1,%2,%3},[%4];"
        : "=r"(r[0]),"=r"(r[1]),"=r"(r[2]),"=r"(r[3]) : "r"(a));
}
__device__ __forceinline__ void ldsm2(uint32_t* r, uint32_t a){
    asm volatile("ldmatrix.sync.aligned.m8n8.x2.shared.b16 {%0,%1},[%2];"
        : "=r"(r[0]),"=r"(r[1]) : "r"(a));
}
__device__ __forceinline__ void mma16816(float* c, const uint32_t* a, const uint32_t* b){
    asm volatile("mma.sync.aligned.m16n8k16.row.col.f32.f16.f16.f32 "
        "{%0,%1,%2,%3},{%4,%5,%6,%7},{%8,%9},{%0,%1,%2,%3};"
        : "+f"(c[0]),"+f"(c[1]),"+f"(c[2]),"+f"(c[3])
        : "r"(a[0]),"r"(a[1]),"r"(a[2]),"r"(a[3]),"r"(b[0]),"r"(b[1]));
}
#define CPA(dst,src) asm volatile("cp.async.cg.shared.global [%0],[%1],16;" :: "r"(dst),"l"(src))
#define CPC() asm volatile("cp.async.commit_group;" ::: "memory")
#define CPW(n) asm volatile("cp.async.wait_group %0;" :: "n"(n) : "memory")

// ---------------- K0: fp32 -> fp16 ----------------
__global__ void __launch_bounds__(256) k_cvtX(const float* __restrict__ src,
    __half* __restrict__ hi, int n)
{
    int i = (blockIdx.x*256 + threadIdx.x)*4;
    if (i >= n) return;
    float4 v = *(const float4*)(src + i);
    *(__half2*)(hi+i)   = __halves2half2(__float2half_rn(v.x), __float2half_rn(v.y));
    *(__half2*)(hi+i+2) = __halves2half2(__float2half_rn(v.z), __float2half_rn(v.w));
}
__global__ void __launch_bounds__(256) k_cvtW3(const float* __restrict__ w0,
    const float* __restrict__ w1, const float* __restrict__ w2, __half* __restrict__ hi)
{
    const float* src = (blockIdx.y==0)?w0:(blockIdx.y==1)?w1:w2;
    __half* dst = hi + (size_t)blockIdx.y*HIDN*HIDN;
    int i = (blockIdx.x*256 + threadIdx.x)*4;
    float4 v = *(const float4*)(src + i);
    *(__half2*)(dst+i)   = __halves2half2(__float2half_rn(v.x), __float2half_rn(v.y));
    *(__half2*)(dst+i+2) = __halves2half2(__float2half_rn(v.z), __float2half_rn(v.w));
}

// ---------------- K1: qkv GEMM, fp16, BK=32/stage, 4-stage, 2 CTA/SM ----------------
#define QROW 80
#define QMAT 10240
#define STG_B 20480
#define QSMEM (4*STG_B)

__global__ void __launch_bounds__(256,2) k_qkv()
{
    extern __shared__ __align__(16) char qs[];
    const int t = threadIdx.x, wid = t>>5, lam = t&31;
    const int z = blockIdx.z, n0 = blockIdx.x*128, m0 = blockIdx.y*128;
    const uint32_t sb = smem_u32(qs);
    const int r = t>>1, q = t&1;
    const __half* Ah = g_Xhi + (size_t)(m0+r)*HIDN + q*16;
    const __half* Bh = g_Whi + (size_t)z*HIDN*HIDN + (size_t)(n0+r)*HIDN + q*16;
    const uint32_t soff = (uint32_t)(r*QROW + q*32);

    float acc[4][4][4] = {};
    const int wm = (wid>>2)*64, wn = (wid&3)*32;
    const uint32_t a_l = (uint32_t)((lam & 15)*QROW + (lam>>4)*16);
    const uint32_t b_l = (uint32_t)((lam & 7)*QROW + ((lam>>3)&1)*16);

#define ISSUE(s_) do{ uint32_t ds = sb + (uint32_t)(((s_)&3)*STG_B) + soff; int k0 = (s_)*32; \
    CPA(ds, Ah + k0); CPA(ds+16, Ah + k0 + 8); \
    CPA(ds+QMAT, Bh + k0); CPA(ds+QMAT+16, Bh + k0 + 8); CPC(); }while(0)

    ISSUE(0); ISSUE(1); ISSUE(2);
    for (int s = 0; s < 32; s++){
        CPW(2);
        __syncthreads();
        if (s < 29) ISSUE(s+3); else CPC();
        uint32_t cb = sb + (uint32_t)((s&3)*STG_B);
#pragma unroll
        for (int kk = 0; kk < 2; kk++){
            uint32_t ko = (uint32_t)(kk*32);
            uint32_t bh4[4][2];
#pragma unroll
            for (int ni = 0; ni < 4; ni++){
                ldsm2(bh4[ni], cb + QMAT + (uint32_t)(wn + ni*8)*QROW + b_l + ko);
            }
#pragma unroll
            for (int mi = 0; mi < 4; mi++){
                uint32_t ah[4];
                ldsm4(ah, cb + (uint32_t)(wm + mi*16)*QROW + a_l + ko);
#pragma unroll
                for (int ni = 0; ni < 4; ni++){
                    mma16816(acc[mi][ni], ah, bh4[ni]);
                }
            }
        }
    }
#undef ISSUE
    float* C = g_qkv + (size_t)z*MM*HIDN;
    const int rr = lam>>2, cc2 = (lam&3)*2;
#pragma unroll
    for (int mi = 0; mi < 4; mi++){
        int row0 = m0 + wm + mi*16 + rr;
#pragma unroll
        for (int ni = 0; ni < 4; ni++){
            int col = n0 + wn + ni*8 + cc2;
            *(float2*)&C[(size_t)row0*HIDN + col]     = make_float2(acc[mi][ni][0], acc[mi][ni][1]);
            *(float2*)&C[(size_t)(row0+8)*HIDN + col] = make_float2(acc[mi][ni][2], acc[mi][ni][3]);
        }
    }
}

// ---------------- K2: gate projections + fused suffix weights ----------------
__global__ void __launch_bounds__(256) k_gate(
    const float* __restrict__ X,
    const float* __restrict__ mdw, const float* __restrict__ mdb,
    const float* __restrict__ sw,  const float* __restrict__ sb,
    const float* __restrict__ lw,  const float* __restrict__ lb)
{
    __shared__ float As[16][68];
    __shared__ float Bg[16][52];
    __shared__ float gv[32][68];
    const int m0 = blockIdx.x * 64;
    const int t = threadIdx.x;
    const int lr = t >> 2, lk = (t & 3) * 4;
    const int ty = t >> 4, tx = t & 15;
    float acc[4][3] = {};
    const float* Arow = X + (size_t)(m0 + lr) * HIDN + lk;
    for (int k0 = 0; k0 < HIDN; k0 += 16){
        float4 av = *(const float4*)(Arow + k0);
        As[lk+0][lr]=av.x; As[lk+1][lr]=av.y; As[lk+2][lr]=av.z; As[lk+3][lr]=av.w;
        if (t < 192){
#pragma unroll
            for (int j = 0; j < 4; j++){
                int idx = t*4+j, n = idx>>4, k = idx&15;
                const float* wp = (n<16)?(mdw+(size_t)n*HIDN):(n<32)?(sw+(size_t)(n-16)*HIDN):(lw+(size_t)(n-32)*HIDN);
                Bg[k][n] = wp[k0+k];
            }
        }
        __syncthreads();
#pragma unroll
        for (int kk = 0; kk < 16; kk++){
            float4 a = *(const float4*)&As[kk][ty*4];
            float ar[4] = {a.x,a.y,a.z,a.w};
            float b0=Bg[kk][tx*3], b1=Bg[kk][tx*3+1], b2=Bg[kk][tx*3+2];
#pragma unroll
            for (int i = 0; i < 4; i++){ acc[i][0]+=ar[i]*b0; acc[i][1]+=ar[i]*b1; acc[i][2]+=ar[i]*b2; }
        }
        __syncthreads();
    }
    const int b = m0 >> 12, l0 = m0 & (LL-1);
#pragma unroll
    for (int i = 0; i < 4; i++)
#pragma unroll
        for (int j = 0; j < 3; j++){
            int li = ty*4 + i, o = tx*3 + j;
            float bias = (o<16)?mdb[o]:(o<32)?sb[o-16]:lb[o-32];
            float v = sigmf(acc[i][j] + bias);
            int g = o >> 4, hh = o & 15;
            float gvv = (g==0)?(1.0f-v):v;
            g_gate[(size_t)g*NGATE + ((size_t)(b*HH+hh))*LL + l0 + li] = gvv;
            if (g < 2) gv[g*16+hh][li] = gvv;
        }
    __syncthreads();
    if (t < 32){
        int hh = t & 15, g = t >> 4;
        int ch = l0 >> 6;
        float* row = g_wt + (size_t)(((b*HH+hh)*64) + ch)*132;
        float wv = 1.0f;
        row[g*64 + 63] = 1.0f;
        for (int j = 62; j >= 0; j--){ wv *= gv[t][j+1]; row[g*64 + j] = wv; }
        row[128+g] = wv * gv[t][0];
        if (g == 0){ row[130] = 0.0f; row[131] = 0.0f; }
    }
}

// ---------------- K3: causal conv + silu (+rmsnorm), 8 timesteps ----------------
#define CT 8
__global__ void __launch_bounds__(256) k_conv(
    const float* __restrict__ cqw, const float* __restrict__ cqb,
    const float* __restrict__ ckw, const float* __restrict__ ckb,
    const float* __restrict__ cvw, const float* __restrict__ cvb,
    const float* __restrict__ qnw, const float* __restrict__ knw)
{
    const int z = blockIdx.z, b = blockIdx.y, l0 = blockIdx.x*CT;
    const float* w    = (z==0)?cqw:(z==1)?ckw:cvw;
    const float* bias = (z==0)?cqb:(z==1)?ckb:cvb;
    const float* src = g_qkv + (size_t)z*MM*HIDN + (size_t)b*LL*HIDN;
    __shared__ float rows[CT+3][1024];
    __shared__ float hs[CT*16];
    const int t = threadIdx.x;
    if (t < CT*16) hs[t] = 0.0f;
    for (int e = t; e < (CT+3)*256; e += 256){
        int j = e>>8, c4 = (e&255)*4;
        int ls = l0 - 3 + j;
        float4 v = (ls >= 0) ? *(const float4*)(src + (size_t)ls*HIDN + c4) : make_float4(0,0,0,0);
        *(float4*)&rows[j][c4] = v;
    }
    __syncthreads();
    const int c0 = t*4, head = c0>>6, d0 = c0&63;
    float4 w0 = *(const float4*)&w[(c0+0)*4];
    float4 w1 = *(const float4*)&w[(c0+1)*4];
    float4 w2 = *(const float4*)&w[(c0+2)*4];
    float4 w3 = *(const float4*)&w[(c0+3)*4];
    float4 bz = *(const float4*)&bias[c0];
    float y[CT][4];
#pragma unroll
    for (int li = 0; li < CT; li++){
        float a0=bz.x, a1=bz.y, a2=bz.z, a3=bz.w;
#pragma unroll
        for (int k = 0; k < 4; k++){
            float4 x = *(const float4*)&rows[li + k][c0];
            a0 += ((const float*)&w0)[k]*x.x; a1 += ((const float*)&w1)[k]*x.y;
            a2 += ((const float*)&w2)[k]*x.z; a3 += ((const float*)&w3)[k]*x.w;
        }
        a0 *= sigmf(a0); a1 *= sigmf(a1); a2 *= sigmf(a2); a3 *= sigmf(a3);
        y[li][0]=a0; y[li][1]=a1; y[li][2]=a2; y[li][3]=a3;
        if (z < 2) atomicAdd(&hs[li*16+head], a0*a0+a1*a1+a2*a2+a3*a3);
    }
    __syncthreads();
#pragma unroll
    for (int li = 0; li < CT; li++){
        float4 o;
        if (z < 2){
            float sc = rsqrtf(hs[li*16+head]*(1.0f/64.0f) + EPSF);
            const float* nw = (z==0)?qnw:knw;
            o = make_float4(y[li][0]*sc*nw[d0], y[li][1]*sc*nw[d0+1], y[li][2]*sc*nw[d0+2], y[li][3]*sc*nw[d0+3]);
        } else {
            o = make_float4(y[li][0], y[li][1], y[li][2], y[li][3]);
        }
        *(float4*)(g_proc + (size_t)z*NPROC + (((size_t)(b*HH+head))*LL + l0+li)*DD + d0) = o;
    }
}

// ---------------- K4: cluster-2 scan, fused B+H, rank-1 Zq/y correction ----------------
#define OW1 0
#define OW2 8448
#define OW2T 17152
#define OZ1 25600
#define OX1 29824
#define OG  34048
#define OKC 36224
#define OQC 40576
#define OPXM 44928
#define OPKM 46976
#define OPW1 47232
#define OPW2 49280
#define OEXC 50304
#define OLW 51072
#define OVV 51488
#define SCAN_BYTES ((OVV + 384)*4)

__global__ void __launch_bounds__(512,1) __cluster_dims__(2,1,1) k_scan(
    const float* __restrict__ W1g, const float* __restrict__ W2g, float* __restrict__ out)
{
    extern __shared__ float sm[];
    float* sW1  = sm + OW1;
    float* sW2  = sm + OW2;
    float* sW2T = sm + OW2T;
    float* sZ1  = sm + OZ1;
    float* sX1  = sm + OX1;
    float* sG   = sm + OG;
    float* pXm  = sm + OPXM;
    float* pKm  = sm + OPKM;
    float* pW1  = sm + OPW1;
    float* pW2  = sm + OPW2;
    float* exch = sm + OEXC;
    float* sW1s = sm + OVV;  float* sW2s = sW1s+128; float* sKm = sW2s+64; float* sXm = sKm+64;

    const int t = threadIdx.x;
    const int bh = blockIdx.x >> 1;
    const uint32_t rank = blockIdx.x & 1, prank = rank ^ 1;
    const int b = bh >> 4, h = bh & 15;
    const int ro = rank*32;
    const float* qp = g_proc + 0*NPROC + (size_t)bh*LL*DD;
    const float* kp = g_proc + 1*NPROC + (size_t)bh*LL*DD;
    const float* vp = g_proc + 2*NPROC + (size_t)bh*LL*DD;
    const float* glr = g_gate + 2*NGATE + (size_t)bh*LL;

    for (int e = t; e < DD*DMM; e += 512){ int d=e>>7, c=e&127; sW1[d*132+c] = W1g[(size_t)h*DD*DMM+e]; }
    for (int e = t; e < DMM*DD; e += 512){ int c=e>>6, d=e&63; float v=W2g[(size_t)h*DMM*DD+e]; sW2[c*68+d]=v; sW2T[d*132+c]=v; }
    if (t < 128){ sW1s[t]=0.0f; sXm[t]=0.0f; }
    if (t < 64){ sW2s[t]=0.0f; sKm[t]=0.0f; }

    const uint32_t kc_u = smem_u32(sm+OKC), qc_u = smem_u32(sm+OQC), lw_u = smem_u32(sm+OLW);
    const uint32_t exc_base = smem_u32(exch);
    const int pfi = t>>4, pfc = (t&15)*16;

#define PF(ch_) do{ int pn=(ch_)&1; int lb=(ch_)*CSZ+ro; \
    CPA(kc_u + pn*8704 + pfi*272 + pfc, kp + (size_t)(lb+pfi)*DD + (pfc>>2)); \
    CPA(qc_u + pn*8704 + pfi*272 + pfc, qp + (size_t)(lb+pfi)*DD + (pfc>>2)); \
    if (t < 16) CPA(lw_u + pn*832 + t*16, glr + (size_t)(ch_)*CSZ + t*4); \
    if (t < 33) CPA(lw_u + pn*832 + 256 + t*16, g_wt + (size_t)(bh*64+(ch_))*132 + t*4); \
    CPC(); }while(0)

    PF(0);
    CPW(0);
    __syncthreads();

    const int rg = t>>5;
    const int r0 = rg*2;
    const int c0 = (t&31)*4;
    const int c2 = (t&31)*2;
    const int l2 = (t&31)*2;

    for (int ch = 0; ch < NCH; ch++){
        const int l0 = ch*CSZ;
        const int par = ch & 1;
        float* kcb = sm + OKC + par*2176;
        float* qcb = sm + OQC + par*2176;
        float* lw  = sm + OLW + par*208;
        float* sLr = lw; float* sWt = lw+64; float* sWs = lw+128;

        float vcr[2][2];
#pragma unroll
        for (int i = 0; i < 2; i++){
            float2 vv = *(const float2*)(vp + (size_t)(l0+ro+r0+i)*DD + c2);
            vcr[i][0]=vv.x; vcr[i][1]=vv.y;
        }

        // ---- B+H fused ----
        float zqo[2][4];
        {
            ull accK[2][2] = {}, accQ[2][2] = {};
            for (int d = 0; d < DD; d += 2){
                float2 k0v = *(const float2*)&kcb[r0*68+d];
                float2 k1v = *(const float2*)&kcb[(r0+1)*68+d];
                float2 q0v = *(const float2*)&qcb[r0*68+d];
                float2 q1v = *(const float2*)&qcb[(r0+1)*68+d];
                ulonglong2 b0 = *(const ulonglong2*)&sW1[d*132+c0];
                ulonglong2 b1 = *(const ulonglong2*)&sW1[(d+1)*132+c0];
                FMA2(accK[0][0],dup2(k0v.x),b0.x); FMA2(accK[0][1],dup2(k0v.x),b0.y);
                FMA2(accK[1][0],dup2(k1v.x),b0.x); FMA2(accK[1][1],dup2(k1v.x),b0.y);
                FMA2(accQ[0][0],dup2(q0v.x),b0.x); FMA2(accQ[0][1],dup2(q0v.x),b0.y);
                FMA2(accQ[1][0],dup2(q1v.x),b0.x); FMA2(accQ[1][1],dup2(q1v.x),b0.y);
                FMA2(accK[0][0],dup2(k0v.y),b1.x); FMA2(accK[0][1],dup2(k0v.y),b1.y);
                FMA2(accK[1][0],dup2(k1v.y),b1.x); FMA2(accK[1][1],dup2(k1v.y),b1.y);
                FMA2(accQ[0][0],dup2(q0v.y),b1.x); FMA2(accQ[0][1],dup2(q0v.y),b1.y);
                FMA2(accQ[1][0],dup2(q1v.y),b1.x); FMA2(accQ[1][1],dup2(q1v.y),b1.y);
            }
            float px[4] = {0,0,0,0};
#pragma unroll
            for (int i = 0; i < 2; i++){
                float2 p = unp(accK[i][0]), qq = unp(accK[i][1]);
                float xv[4] = {p.x*sigmf(p.x), p.y*sigmf(p.y), qq.x*sigmf(qq.x), qq.y*sigmf(qq.y)};
                *(float4*)&sZ1[(r0+i)*132+c0] = make_float4(p.x,p.y,qq.x,qq.y);
                *(float4*)&sX1[(r0+i)*132+c0] = make_float4(xv[0],xv[1],xv[2],xv[3]);
                float wv = sWt[ro+r0+i];
#pragma unroll
                for (int j = 0; j < 4; j++) px[j] += wv*xv[j];
                float2 pq = unp(accQ[i][0]), qqq = unp(accQ[i][1]);
                zqo[i][0]=pq.x; zqo[i][1]=pq.y; zqo[i][2]=qqq.x; zqo[i][3]=qqq.y;
            }
            *(float4*)&pXm[rg*128+c0] = make_float4(px[0],px[1],px[2],px[3]);
            if (t < 256){
                int i0 = (t>>6)*8, dd = t&63;
                float s = 0.0f;
#pragma unroll
                for (int j = 0; j < 8; j++) s += sWt[ro+i0+j]*kcb[(i0+j)*68+dd];
                pKm[(t>>6)*64+dd] = s;
            }
        }
        __syncwarp();

        // ---- C ----
        {
            ull acc[2] = {};
            for (int cc = 0; cc < DMM; cc += 4){
                float4 a0 = *(const float4*)&sX1[(r0+0)*132+cc];
                float4 a1 = *(const float4*)&sX1[(r0+1)*132+cc];
#pragma unroll
                for (int u = 0; u < 4; u++){
                    ull bv = *(const ull*)&sW2[(cc+u)*68+c2];
                    float e0 = u==0?a0.x:u==1?a0.y:u==2?a0.z:a0.w;
                    float e1 = u==0?a1.x:u==1?a1.y:u==2?a1.z:a1.w;
                    FMA2(acc[0],dup2(e0),bv); FMA2(acc[1],dup2(e1),bv);
                }
            }
            float pw[2] = {0,0};
#pragma unroll
            for (int i = 0; i < 2; i++){
                float2 p = unp(acc[i]);
                float g0 = p.x - vcr[i][0], g1 = p.y - vcr[i][1];
                *(float2*)&sG[(r0+i)*68+c2] = make_float2(g0, g1);
                float wl = sWs[ro+r0+i] * (-sLr[ro+r0+i]);
                pw[0] += wl*g0; pw[1] += wl*g1;
            }
            *(float2*)&pW2[rg*64+c2] = make_float2(pw[0], pw[1]);
        }
        __syncwarp();

        // ---- E ----
        {
            ull acc[2][2] = {};
            for (int d = 0; d < DD; d++){
                ull a0 = dup2(sG[(r0+0)*68+d]), a1 = dup2(sG[(r0+1)*68+d]);
                ulonglong2 bv = *(const ulonglong2*)&sW2T[d*132+c0];
                FMA2(acc[0][0],a0,bv.x); FMA2(acc[0][1],a0,bv.y);
                FMA2(acc[1][0],a1,bv.x); FMA2(acc[1][1],a1,bv.y);
            }
            float pw[4] = {0,0,0,0};
#pragma unroll
            for (int i = 0; i < 2; i++){
                float nlr = -sLr[ro+r0+i];
                float ws = sWs[ro+r0+i];
                float2 p = unp(acc[i][0]), qq = unp(acc[i][1]);
                float g[4] = {p.x,p.y,qq.x,qq.y};
#pragma unroll
                for (int j = 0; j < 4; j++){
                    float z = sZ1[(r0+i)*132+c0+j];
                    float sg = sigmf(z);
                    pw[j] += ws * (nlr*g[j]*(sg*(1.0f + z*(1.0f - sg))));
                }
            }
            *(float4*)&pW1[rg*128+c0] = make_float4(pw[0],pw[1],pw[2],pw[3]);
        }
        __syncthreads();

        // ---- R1 ----
        if (t < 384){
            float s = 0.0f;
            if (t < 128){
#pragma unroll
                for (int g = 0; g < 16; g++) s += pXm[g*128+t];
            } else if (t < 192){
                int d = t-128;
#pragma unroll
                for (int g = 0; g < 4; g++) s += pKm[g*64+d];
            } else if (t < 320){
                int c = t-192;
#pragma unroll
                for (int g = 0; g < 16; g++) s += pW1[g*128+c];
            } else {
                int d = t-320;
#pragma unroll
                for (int g = 0; g < 16; g++) s += pW2[g*64+d];
            }
            exch[par*384 + t] = s;
        }
        asm volatile("barrier.cluster.arrive.aligned;" ::: "memory");
        asm volatile("barrier.cluster.wait.aligned;" ::: "memory");

        // ---- R2 ----
        if (t < 384){
            float ov = exch[par*384 + t];
            float pv = ld_peer(exc_base + (uint32_t)(par*384 + t)*4u, prank);
            float v0 = (rank == 0) ? ov : pv;
            float v1 = (rank == 0) ? pv : ov;
            float total = v0 + v1;
            float m0 = lw[192], m1 = lw[193];
            if (t < 128)       sXm[t]      = m0*sXm[t]      + total;
            else if (t < 192)  sKm[t-128]  = m0*sKm[t-128]  + total;
            else if (t < 320)  sW1s[t-192] = m1*sW1s[t-192] + total;
            else               sW2s[t-320] = m1*sW2s[t-320] + total;
        }
        __syncthreads();

        // ---- FIX ----
        float dx0 = 0.0f, dx1 = 0.0f;
        {
            float mp = lw[192];
            float dq0 = qcb[r0*68+l2]*sKm[l2] + qcb[r0*68+l2+1]*sKm[l2+1];
            float dq1 = qcb[(r0+1)*68+l2]*sKm[l2] + qcb[(r0+1)*68+l2+1]*sKm[l2+1];
#pragma unroll
            for (int o = 16; o > 0; o >>= 1){
                dq0 += __shfl_xor_sync(0xffffffffu, dq0, o);
                dq1 += __shfl_xor_sync(0xffffffffu, dq1, o);
            }
            float4 w1sv = *(const float4*)&sW1s[c0];
            float4 xmv  = *(const float4*)&sXm[c0];
#pragma unroll
            for (int i = 0; i < 2; i++){
                float dq = i ? dq1 : dq0;
                float sq[4]; float dx = 0.0f;
#pragma unroll
                for (int j = 0; j < 4; j++){
                    float z = mp*zqo[i][j] + dq*((const float*)&w1sv)[j];
                    float s = z*sigmf(z);
                    sq[j] = s;
                    dx += s*((const float*)&xmv)[j];
                }
                *(float4*)&sX1[(r0+i)*132+c0] = make_float4(sq[0],sq[1],sq[2],sq[3]);
                if (i) dx1 = dx; else dx0 = dx;
            }
#pragma unroll
            for (int o = 16; o > 0; o >>= 1){
                dx0 += __shfl_xor_sync(0xffffffffu, dx0, o);
                dx1 += __shfl_xor_sync(0xffffffffu, dx1, o);
            }
        }
        __syncwarp();

        // ---- I ----
        {
            float mp = lw[192];
            ull acc[2] = {};
            for (int cc = 0; cc < DMM; cc += 4){
                float4 a0 = *(const float4*)&sX1[(r0+0)*132+cc];
                float4 a1 = *(const float4*)&sX1[(r0+1)*132+cc];
#pragma unroll
                for (int u = 0; u < 4; u++){
                    ull bv = *(const ull*)&sW2[(cc+u)*68+c2];
                    float e0 = u==0?a0.x:u==1?a0.y:u==2?a0.z:a0.w;
                    float e1 = u==0?a1.x:u==1?a1.y:u==2?a1.z:a1.w;
                    FMA2(acc[0],dup2(e0),bv); FMA2(acc[1],dup2(e1),bv);
                }
            }
            float w2s0 = sW2s[c2], w2s1 = sW2s[c2+1];
#pragma unroll
            for (int i = 0; i < 2; i++){
                float dx = i ? dx1 : dx0;
                float2 p = unp(acc[i]);
                *(float2*)&sG[(r0+i)*68+c2] =
                    make_float2(mp*p.x + dx*w2s0, mp*p.y + dx*w2s1);
            }
        }
        __syncthreads();

        // ---- store + tail ----
        for (int e = t; e < 32*64; e += 512){
            int d = e>>5, i = e&31;
            out[(size_t)b*LL*HIDN + ((size_t)(h*DD+d))*LL + (l0+ro+i)] = sG[i*68+d];
        }
        if (ch+1 < NCH) PF(ch+1);
        {
            float mp = lw[192];
            for (int e = t; e < DD*DMM; e += 512){
                int d = e>>7, c = e&127;
                sW1[d*132+c] = mp*sW1[d*132+c] + sKm[d]*sW1s[c];
            }
            for (int e = t; e < DMM*DD; e += 512){
                int c = e>>6, d = e&63;
                float v = mp*sW2[c*68+d] + sXm[c]*sW2s[d];
                sW2[c*68+d] = v; sW2T[d*132+c] = v;
            }
        }
        CPW(0);
        __syncthreads();
    }
#undef PF
}

// ---------------- launch (multi-stream fork/join) ----------------
extern "C" void kernel_launch(void* const* d_in, const int* in_sizes, int n_in,
                              void* d_out, int out_size) {
    (void)in_sizes; (void)n_in; (void)out_size;
    const float* X   = (const float*)d_in[0];
    const float* Wq  = (const float*)d_in[1];
    const float* Wk  = (const float*)d_in[2];
    const float* Wv  = (const float*)d_in[3];
    const float* cqw = (const float*)d_in[4];
    const float* cqb = (const float*)d_in[5];
    const float* ckw = (const float*)d_in[6];
    const float* ckb = (const float*)d_in[7];
    const float* cvw = (const float*)d_in[8];
    const float* cvb = (const float*)d_in[9];
    const float* qnw = (const float*)d_in[10];
    const float* knw = (const float*)d_in[11];
    const float* mdw = (const float*)d_in[12];
    const float* mdb = (const float*)d_in[13];
    const float* sw  = (const float*)d_in[14];
    const float* sb  = (const float*)d_in[15];
    const float* lw  = (const float*)d_in[16];
    const float* lb  = (const float*)d_in[17];
    const float* W1g = (const float*)d_in[18];
    const float* W2g = (const float*)d_in[19];
    float* out = (float*)d_out;

    static cudaStream_t s_aux = nullptr;
    static cudaEvent_t e_fork = nullptr, e_join = nullptr;
    if (!s_aux){
        cudaStreamCreateWithFlags(&s_aux, cudaStreamNonBlocking);
        cudaEventCreateWithFlags(&e_fork, cudaEventDisableTiming);
        cudaEventCreateWithFlags(&e_join, cudaEventDisableTiming);
        cudaFuncSetAttribute(k_qkv, cudaFuncAttributeMaxDynamicSharedMemorySize, QSMEM);
        cudaFuncSetAttribute(k_scan, cudaFuncAttributeMaxDynamicSharedMemorySize, SCAN_BYTES);
    }

    __half *xhi, *whi;
    cudaGetSymbolAddress((void**)&xhi, g_Xhi);
    cudaGetSymbolAddress((void**)&whi, g_Whi);

    cudaEventRecord(e_fork, 0);
    cudaStreamWaitEvent(s_aux, e_fork, 0);
    k_gate<<<dim3(MM/64), 256, 0, s_aux>>>(X, mdw, mdb, sw, sb, lw, lb);
    cudaEventRecord(e_join, s_aux);

    k_cvtX<<<MM*HIDN/1024, 256>>>(X, xhi, MM*HIDN);
    k_cvtW3<<<dim3(HIDN*HIDN/1024, 3), 256>>>(Wq, Wk, Wv, whi);
    k_qkv<<<dim3(HIDN/128, MM/128, 3), 256, QSMEM>>>();
    k_conv<<<dim3(LL/CT, BB, 3), 256>>>(cqw, cqb, ckw, ckb, cvw, cvb, qnw, knw);
    cudaStreamWaitEvent(0, e_join, 0);
    k_scan<<<dim3(BB*HH*2), 512, SCAN_BYTES>>>(W1g, W2g, out);
}

// round 16
// speedup vs baseline: 1.0215x; 1.0215x over previous
#include <cuda_runtime.h>
#include <cuda_fp16.h>
#include <math.h>
#include <stdint.h>

#define BB 4
#define LL 4096
#define HIDN 1024
#define HH 16
#define DD 64
#define DMM 128
#define CSZ 64
#define NCH 64
#define MM (BB*LL)
#define EPSF 1e-6f
#define NPROC ((size_t)BB*HH*LL*DD)
#define NGATE ((size_t)BB*HH*LL)

static __device__ float g_qkv [(size_t)3*MM*HIDN];
static __device__ float g_proc[(size_t)3*NPROC];
static __device__ float g_gate[(size_t)3*NGATE];
static __device__ float g_wt  [(size_t)64*64*132];
static __device__ __half g_Xhi[(size_t)MM*HIDN];
static __device__ __half g_Whi[(size_t)3*HIDN*HIDN];

__device__ __forceinline__ float sigmf(float x){ return __fdividef(1.0f, 1.0f + __expf(-x)); }

typedef unsigned long long ull;
#define FMA2(acc,a,b) asm("fma.rn.f32x2 %0,%1,%2,%0;" : "+l"(acc) : "l"(a), "l"(b))
__device__ __forceinline__ ull dup2(float a){ ull r; asm("mov.b64 %0,{%1,%1};" : "=l"(r) : "r"(__float_as_uint(a))); return r; }
__device__ __forceinline__ float2 unp(ull v){ uint32_t l,h; asm("mov.b64 {%0,%1},%2;" : "=r"(l),"=r"(h) : "l"(v)); return make_float2(__uint_as_float(l),__uint_as_float(h)); }
__device__ __forceinline__ uint32_t smem_u32(const void* p){
    uint32_t a; asm("{ .reg .u64 t; cvta.to.shared.u64 t, %1; cvt.u32.u64 %0, t; }" : "=r"(a) : "l"(p)); return a;
}
__device__ __forceinline__ float ld_peer(uint32_t laddr, uint32_t prank){
    uint32_t ra; float v;
    asm("mapa.shared::cluster.u32 %0,%1,%2;" : "=r"(ra) : "r"(laddr), "r"(prank));
    asm volatile("ld.shared::cluster.f32 %0,[%1];" : "=f"(v) : "r"(ra));
    return v;
}
__device__ __forceinline__ void ldsm4(uint32_t* r, uint32_t a){
    asm volatile("ldmatrix.sync.aligned.m8n8.x4.shared.b16 {%0,%1,%2,%3},[%4];"
        : "=r"(r[0]),"=r"(r[1]),"=r"(r[2]),"=r"(r[3]) : "r"(a));
}
__device__ __forceinline__ void ldsm2(uint32_t* r, uint32_t a){
    asm volatile("ldmatrix.sync.aligned.m8n8.x2.shared.b16 {%0,%1},[%2];"
        : "=r"(r[0]),"=r"(r[1]) : "r"(a));
}
__device__ __forceinline__ void mma16816(float* c, const uint32_t* a, const uint32_t* b){
    asm volatile("mma.sync.aligned.m16n8k16.row.col.f32.f16.f16.f32 "
        "{%0,%1,%2,%3},{%4,%5,%6,%7},{%8,%9},{%0,%1,%2,%3};"
        : "+f"(c[0]),"+f"(c[1]),"+f"(c[2]),"+f"(c[3])
        : "r"(a[0]),"r"(a[1]),"r"(a[2]),"r"(a[3]),"r"(b[0]),"r"(b[1]));
}
#define CPA(dst,src) asm volatile("cp.async.cg.shared.global [%0],[%1],16;" :: "r"(dst),"l"(src))
#define CPC() asm volatile("cp.async.commit_group;" ::: "memory")
#define CPW(n) asm volatile("cp.async.wait_group %0;" :: "n"(n) : "memory")

// ---------------- K0: fp32 -> fp16 ----------------
__global__ void __launch_bounds__(256) k_cvtX(const float* __restrict__ src,
    __half* __restrict__ hi, int n)
{
    int i = (blockIdx.x*256 + threadIdx.x)*4;
    if (i >= n) return;
    float4 v = *(const float4*)(src + i);
    *(__half2*)(hi+i)   = __halves2half2(__float2half_rn(v.x), __float2half_rn(v.y));
    *(__half2*)(hi+i+2) = __halves2half2(__float2half_rn(v.z), __float2half_rn(v.w));
}
__global__ void __launch_bounds__(256) k_cvtW3(const float* __restrict__ w0,
    const float* __restrict__ w1, const float* __restrict__ w2, __half* __restrict__ hi)
{
    const float* src = (blockIdx.y==0)?w0:(blockIdx.y==1)?w1:w2;
    __half* dst = hi + (size_t)blockIdx.y*HIDN*HIDN;
    int i = (blockIdx.x*256 + threadIdx.x)*4;
    float4 v = *(const float4*)(src + i);
    *(__half2*)(dst+i)   = __halves2half2(__float2half_rn(v.x), __float2half_rn(v.y));
    *(__half2*)(dst+i+2) = __halves2half2(__float2half_rn(v.z), __float2half_rn(v.w));
}

// ---------------- K1: qkv GEMM, fp16 1-term, BK=16, 4-stage, 2 CTA/SM (R14 proven) ----------------
#define STG_B 12288
#define QSMEM (4*STG_B)

__global__ void __launch_bounds__(256,2) k_qkv()
{
    extern __shared__ __align__(16) char qs[];
    const int t = threadIdx.x, wid = t>>5, lam = t&31;
    const int z = blockIdx.z, n0 = blockIdx.x*128, m0 = blockIdx.y*128;
    const uint32_t sb = smem_u32(qs);
    const int r = t>>1, q = t&1;
    const __half* Ah = g_Xhi + (size_t)(m0+r)*HIDN + q*8;
    const __half* Bh = g_Whi + (size_t)z*HIDN*HIDN + (size_t)(n0+r)*HIDN + q*8;
    const uint32_t soff = (uint32_t)(r*48 + q*16);

    float acc[4][4][4] = {};
    const int wm = (wid>>2)*64, wn = (wid&3)*32;
    const uint32_t a_l = (uint32_t)((lam & 15)*48 + (lam>>4)*16);
    const uint32_t b_l = (uint32_t)((lam & 7)*48 + ((lam>>3)&1)*16);

#define ISSUE(s_) do{ uint32_t ds = sb + (uint32_t)(((s_)&3)*STG_B) + soff; int k0 = (s_)*16; \
    CPA(ds, Ah + k0); CPA(ds+6144, Bh + k0); CPC(); }while(0)

    ISSUE(0); ISSUE(1); ISSUE(2);
    for (int s = 0; s < 64; s++){
        CPW(2);
        __syncthreads();
        if (s < 61) ISSUE(s+3); else CPC();
        uint32_t cb = sb + (uint32_t)((s&3)*STG_B);
        uint32_t bh4[4][2];
#pragma unroll
        for (int ni = 0; ni < 4; ni++){
            ldsm2(bh4[ni], cb + 6144 + (uint32_t)(wn + ni*8)*48 + b_l);
        }
#pragma unroll
        for (int mi = 0; mi < 4; mi++){
            uint32_t ah[4];
            ldsm4(ah, cb + (uint32_t)(wm + mi*16)*48 + a_l);
#pragma unroll
            for (int ni = 0; ni < 4; ni++){
                mma16816(acc[mi][ni], ah, bh4[ni]);
            }
        }
    }
#undef ISSUE
    float* C = g_qkv + (size_t)z*MM*HIDN;
    const int rr = lam>>2, cc2 = (lam&3)*2;
#pragma unroll
    for (int mi = 0; mi < 4; mi++){
        int row0 = m0 + wm + mi*16 + rr;
#pragma unroll
        for (int ni = 0; ni < 4; ni++){
            int col = n0 + wn + ni*8 + cc2;
            *(float2*)&C[(size_t)row0*HIDN + col]     = make_float2(acc[mi][ni][0], acc[mi][ni][1]);
            *(float2*)&C[(size_t)(row0+8)*HIDN + col] = make_float2(acc[mi][ni][2], acc[mi][ni][3]);
        }
    }
}

// ---------------- K2: gate projections + fused suffix weights ----------------
__global__ void __launch_bounds__(256) k_gate(
    const float* __restrict__ X,
    const float* __restrict__ mdw, const float* __restrict__ mdb,
    const float* __restrict__ sw,  const float* __restrict__ sb,
    const float* __restrict__ lw,  const float* __restrict__ lb)
{
    __shared__ float As[16][68];
    __shared__ float Bg[16][52];
    __shared__ float gv[32][68];
    const int m0 = blockIdx.x * 64;
    const int t = threadIdx.x;
    const int lr = t >> 2, lk = (t & 3) * 4;
    const int ty = t >> 4, tx = t & 15;
    float acc[4][3] = {};
    const float* Arow = X + (size_t)(m0 + lr) * HIDN + lk;
    for (int k0 = 0; k0 < HIDN; k0 += 16){
        float4 av = *(const float4*)(Arow + k0);
        As[lk+0][lr]=av.x; As[lk+1][lr]=av.y; As[lk+2][lr]=av.z; As[lk+3][lr]=av.w;
        if (t < 192){
#pragma unroll
            for (int j = 0; j < 4; j++){
                int idx = t*4+j, n = idx>>4, k = idx&15;
                const float* wp = (n<16)?(mdw+(size_t)n*HIDN):(n<32)?(sw+(size_t)(n-16)*HIDN):(lw+(size_t)(n-32)*HIDN);
                Bg[k][n] = wp[k0+k];
            }
        }
        __syncthreads();
#pragma unroll
        for (int kk = 0; kk < 16; kk++){
            float4 a = *(const float4*)&As[kk][ty*4];
            float ar[4] = {a.x,a.y,a.z,a.w};
            float b0=Bg[kk][tx*3], b1=Bg[kk][tx*3+1], b2=Bg[kk][tx*3+2];
#pragma unroll
            for (int i = 0; i < 4; i++){ acc[i][0]+=ar[i]*b0; acc[i][1]+=ar[i]*b1; acc[i][2]+=ar[i]*b2; }
        }
        __syncthreads();
    }
    const int b = m0 >> 12, l0 = m0 & (LL-1);
#pragma unroll
    for (int i = 0; i < 4; i++)
#pragma unroll
        for (int j = 0; j < 3; j++){
            int li = ty*4 + i, o = tx*3 + j;
            float bias = (o<16)?mdb[o]:(o<32)?sb[o-16]:lb[o-32];
            float v = sigmf(acc[i][j] + bias);
            int g = o >> 4, hh = o & 15;
            float gvv = (g==0)?(1.0f-v):v;
            g_gate[(size_t)g*NGATE + ((size_t)(b*HH+hh))*LL + l0 + li] = gvv;
            if (g < 2) gv[g*16+hh][li] = gvv;
        }
    __syncthreads();
    if (t < 32){
        int hh = t & 15, g = t >> 4;
        int ch = l0 >> 6;
        float* row = g_wt + (size_t)(((b*HH+hh)*64) + ch)*132;
        float wv = 1.0f;
        row[g*64 + 63] = 1.0f;
        for (int j = 62; j >= 0; j--){ wv *= gv[t][j+1]; row[g*64 + j] = wv; }
        row[128+g] = wv * gv[t][0];
        if (g == 0){ row[130] = 0.0f; row[131] = 0.0f; }
    }
}

// ---------------- K3: causal conv + silu (+rmsnorm), 8 timesteps ----------------
#define CT 8
__global__ void __launch_bounds__(256) k_conv(
    const float* __restrict__ cqw, const float* __restrict__ cqb,
    const float* __restrict__ ckw, const float* __restrict__ ckb,
    const float* __restrict__ cvw, const float* __restrict__ cvb,
    const float* __restrict__ qnw, const float* __restrict__ knw)
{
    const int z = blockIdx.z, b = blockIdx.y, l0 = blockIdx.x*CT;
    const float* w    = (z==0)?cqw:(z==1)?ckw:cvw;
    const float* bias = (z==0)?cqb:(z==1)?ckb:cvb;
    const float* src = g_qkv + (size_t)z*MM*HIDN + (size_t)b*LL*HIDN;
    __shared__ float rows[CT+3][1024];
    __shared__ float hs[CT*16];
    const int t = threadIdx.x;
    if (t < CT*16) hs[t] = 0.0f;
    for (int e = t; e < (CT+3)*256; e += 256){
        int j = e>>8, c4 = (e&255)*4;
        int ls = l0 - 3 + j;
        float4 v = (ls >= 0) ? *(const float4*)(src + (size_t)ls*HIDN + c4) : make_float4(0,0,0,0);
        *(float4*)&rows[j][c4] = v;
    }
    __syncthreads();
    const int c0 = t*4, head = c0>>6, d0 = c0&63;
    float4 w0 = *(const float4*)&w[(c0+0)*4];
    float4 w1 = *(const float4*)&w[(c0+1)*4];
    float4 w2 = *(const float4*)&w[(c0+2)*4];
    float4 w3 = *(const float4*)&w[(c0+3)*4];
    float4 bz = *(const float4*)&bias[c0];
    float y[CT][4];
#pragma unroll
    for (int li = 0; li < CT; li++){
        float a0=bz.x, a1=bz.y, a2=bz.z, a3=bz.w;
#pragma unroll
        for (int k = 0; k < 4; k++){
            float4 x = *(const float4*)&rows[li + k][c0];
            a0 += ((const float*)&w0)[k]*x.x; a1 += ((const float*)&w1)[k]*x.y;
            a2 += ((const float*)&w2)[k]*x.z; a3 += ((const float*)&w3)[k]*x.w;
        }
        a0 *= sigmf(a0); a1 *= sigmf(a1); a2 *= sigmf(a2); a3 *= sigmf(a3);
        y[li][0]=a0; y[li][1]=a1; y[li][2]=a2; y[li][3]=a3;
        if (z < 2) atomicAdd(&hs[li*16+head], a0*a0+a1*a1+a2*a2+a3*a3);
    }
    __syncthreads();
#pragma unroll
    for (int li = 0; li < CT; li++){
        float4 o;
        if (z < 2){
            float sc = rsqrtf(hs[li*16+head]*(1.0f/64.0f) + EPSF);
            const float* nw = (z==0)?qnw:knw;
            o = make_float4(y[li][0]*sc*nw[d0], y[li][1]*sc*nw[d0+1], y[li][2]*sc*nw[d0+2], y[li][3]*sc*nw[d0+3]);
        } else {
            o = make_float4(y[li][0], y[li][1], y[li][2], y[li][3]);
        }
        *(float4*)(g_proc + (size_t)z*NPROC + (((size_t)(b*HH+head))*LL + l0+li)*DD + d0) = o;
    }
}

// ---------------- K4: cluster-2 scan, fused B+H, rank-1 fix, Z1-in-regs ----------------
#define OW1 0
#define OW2 8448
#define OW2T 17152
#define OX1 25600
#define OG  29824
#define OKC 32000
#define OQC 36352
#define OPXM 40704
#define OPKM 42752
#define OPW1 43008
#define OPW2 45056
#define OEXC 46080
#define OLW 46848
#define OVV 47264
#define SCAN_BYTES ((OVV + 384)*4)

__global__ void __launch_bounds__(512,1) __cluster_dims__(2,1,1) k_scan(
    const float* __restrict__ W1g, const float* __restrict__ W2g, float* __restrict__ out)
{
    extern __shared__ float sm[];
    float* sW1  = sm + OW1;
    float* sW2  = sm + OW2;
    float* sW2T = sm + OW2T;
    float* sX1  = sm + OX1;   // [32][132] X1, later sq
    float* sG   = sm + OG;    // [32][68]  g0, later y
    float* pXm  = sm + OPXM;
    float* pKm  = sm + OPKM;
    float* pW1  = sm + OPW1;
    float* pW2  = sm + OPW2;
    float* exch = sm + OEXC;
    float* sW1s = sm + OVV;  float* sW2s = sW1s+128; float* sKm = sW2s+64; float* sXm = sKm+64;

    const int t = threadIdx.x;
    const int bh = blockIdx.x >> 1;
    const uint32_t rank = blockIdx.x & 1, prank = rank ^ 1;
    const int b = bh >> 4, h = bh & 15;
    const int ro = rank*32;
    const float* qp = g_proc + 0*NPROC + (size_t)bh*LL*DD;
    const float* kp = g_proc + 1*NPROC + (size_t)bh*LL*DD;
    const float* vp = g_proc + 2*NPROC + (size_t)bh*LL*DD;
    const float* glr = g_gate + 2*NGATE + (size_t)bh*LL;

    for (int e = t; e < DD*DMM; e += 512){ int d=e>>7, c=e&127; sW1[d*132+c] = W1g[(size_t)h*DD*DMM+e]; }
    for (int e = t; e < DMM*DD; e += 512){ int c=e>>6, d=e&63; float v=W2g[(size_t)h*DMM*DD+e]; sW2[c*68+d]=v; sW2T[d*132+c]=v; }
    if (t < 128){ sW1s[t]=0.0f; sXm[t]=0.0f; }
    if (t < 64){ sW2s[t]=0.0f; sKm[t]=0.0f; }

    const uint32_t kc_u = smem_u32(sm+OKC), qc_u = smem_u32(sm+OQC), lw_u = smem_u32(sm+OLW);
    const uint32_t exc_base = smem_u32(exch);
    const int pfi = t>>4, pfc = (t&15)*16;

#define PF(ch_) do{ int pn=(ch_)&1; int lb=(ch_)*CSZ+ro; \
    CPA(kc_u + pn*8704 + pfi*272 + pfc, kp + (size_t)(lb+pfi)*DD + (pfc>>2)); \
    CPA(qc_u + pn*8704 + pfi*272 + pfc, qp + (size_t)(lb+pfi)*DD + (pfc>>2)); \
    if (t < 16) CPA(lw_u + pn*832 + t*16, glr + (size_t)(ch_)*CSZ + t*4); \
    if (t < 33) CPA(lw_u + pn*832 + 256 + t*16, g_wt + (size_t)(bh*64+(ch_))*132 + t*4); \
    CPC(); }while(0)

    PF(0);
    CPW(0);
    __syncthreads();

    const int rg = t>>5;
    const int r0 = rg*2;
    const int c0 = (t&31)*4;
    const int c2 = (t&31)*2;
    const int l2 = (t&31)*2;

    for (int ch = 0; ch < NCH; ch++){
        const int l0 = ch*CSZ;
        const int par = ch & 1;
        float* kcb = sm + OKC + par*2176;
        float* qcb = sm + OQC + par*2176;
        float* lw  = sm + OLW + par*208;
        float* sLr = lw; float* sWt = lw+64; float* sWs = lw+128;

        float vcr[2][2];
#pragma unroll
        for (int i = 0; i < 2; i++){
            float2 vv = *(const float2*)(vp + (size_t)(l0+ro+r0+i)*DD + c2);
            vcr[i][0]=vv.x; vcr[i][1]=vv.y;
        }

        // ---- B+H fused: Z1 kept in regs; ZqO in regs ----
        float zqo[2][4], z1r[2][4];
        {
            ull accK[2][2] = {}, accQ[2][2] = {};
            for (int d = 0; d < DD; d += 2){
                float2 k0v = *(const float2*)&kcb[r0*68+d];
                float2 k1v = *(const float2*)&kcb[(r0+1)*68+d];
                float2 q0v = *(const float2*)&qcb[r0*68+d];
                float2 q1v = *(const float2*)&qcb[(r0+1)*68+d];
                ulonglong2 b0 = *(const ulonglong2*)&sW1[d*132+c0];
                ulonglong2 b1 = *(const ulonglong2*)&sW1[(d+1)*132+c0];
                FMA2(accK[0][0],dup2(k0v.x),b0.x); FMA2(accK[0][1],dup2(k0v.x),b0.y);
                FMA2(accK[1][0],dup2(k1v.x),b0.x); FMA2(accK[1][1],dup2(k1v.x),b0.y);
                FMA2(accQ[0][0],dup2(q0v.x),b0.x); FMA2(accQ[0][1],dup2(q0v.x),b0.y);
                FMA2(accQ[1][0],dup2(q1v.x),b0.x); FMA2(accQ[1][1],dup2(q1v.x),b0.y);
                FMA2(accK[0][0],dup2(k0v.y),b1.x); FMA2(accK[0][1],dup2(k0v.y),b1.y);
                FMA2(accK[1][0],dup2(k1v.y),b1.x); FMA2(accK[1][1],dup2(k1v.y),b1.y);
                FMA2(accQ[0][0],dup2(q0v.y),b1.x); FMA2(accQ[0][1],dup2(q0v.y),b1.y);
                FMA2(accQ[1][0],dup2(q1v.y),b1.x); FMA2(accQ[1][1],dup2(q1v.y),b1.y);
            }
            float px[4] = {0,0,0,0};
#pragma unroll
            for (int i = 0; i < 2; i++){
                float2 p = unp(accK[i][0]), qq = unp(accK[i][1]);
                z1r[i][0]=p.x; z1r[i][1]=p.y; z1r[i][2]=qq.x; z1r[i][3]=qq.y;
                float xv[4] = {p.x*sigmf(p.x), p.y*sigmf(p.y), qq.x*sigmf(qq.x), qq.y*sigmf(qq.y)};
                *(float4*)&sX1[(r0+i)*132+c0] = make_float4(xv[0],xv[1],xv[2],xv[3]);
                float wv = sWt[ro+r0+i];
#pragma unroll
                for (int j = 0; j < 4; j++) px[j] += wv*xv[j];
                float2 pq = unp(accQ[i][0]), qqq = unp(accQ[i][1]);
                zqo[i][0]=pq.x; zqo[i][1]=pq.y; zqo[i][2]=qqq.x; zqo[i][3]=qqq.y;
            }
            *(float4*)&pXm[rg*128+c0] = make_float4(px[0],px[1],px[2],px[3]);
            if (t < 256){
                int i0 = (t>>6)*8, dd = t&63;
                float s = 0.0f;
#pragma unroll
                for (int j = 0; j < 8; j++) s += sWt[ro+i0+j]*kcb[(i0+j)*68+dd];
                pKm[(t>>6)*64+dd] = s;
            }
        }
        __syncwarp();

        // ---- C: g0 = X1@W2 - vc -> sG; fold pW2 ----
        {
            ull acc[2] = {};
            for (int cc = 0; cc < DMM; cc += 4){
                float4 a0 = *(const float4*)&sX1[(r0+0)*132+cc];
                float4 a1 = *(const float4*)&sX1[(r0+1)*132+cc];
#pragma unroll
                for (int u = 0; u < 4; u++){
                    ull bv = *(const ull*)&sW2[(cc+u)*68+c2];
                    float e0 = u==0?a0.x:u==1?a0.y:u==2?a0.z:a0.w;
                    float e1 = u==0?a1.x:u==1?a1.y:u==2?a1.z:a1.w;
                    FMA2(acc[0],dup2(e0),bv); FMA2(acc[1],dup2(e1),bv);
                }
            }
            float pw[2] = {0,0};
#pragma unroll
            for (int i = 0; i < 2; i++){
                float2 p = unp(acc[i]);
                float g0 = p.x - vcr[i][0], g1 = p.y - vcr[i][1];
                *(float2*)&sG[(r0+i)*68+c2] = make_float2(g0, g1);
                float wl = sWs[ro+r0+i] * (-sLr[ro+r0+i]);
                pw[0] += wl*g0; pw[1] += wl*g1;
            }
            *(float2*)&pW2[rg*64+c2] = make_float2(pw[0], pw[1]);
        }
        __syncwarp();

        // ---- E: gZ1 = -lr*(g0@W2^T)*silu_bwd(Z1-from-regs); fold pW1 ----
        {
            ull acc[2][2] = {};
            for (int d = 0; d < DD; d += 2){
                float2 g0p = *(const float2*)&sG[(r0+0)*68+d];
                float2 g1p = *(const float2*)&sG[(r0+1)*68+d];
                ulonglong2 b0 = *(const ulonglong2*)&sW2T[d*132+c0];
                ulonglong2 b1 = *(const ulonglong2*)&sW2T[(d+1)*132+c0];
                FMA2(acc[0][0],dup2(g0p.x),b0.x); FMA2(acc[0][1],dup2(g0p.x),b0.y);
                FMA2(acc[1][0],dup2(g1p.x),b0.x); FMA2(acc[1][1],dup2(g1p.x),b0.y);
                FMA2(acc[0][0],dup2(g0p.y),b1.x); FMA2(acc[0][1],dup2(g0p.y),b1.y);
                FMA2(acc[1][0],dup2(g1p.y),b1.x); FMA2(acc[1][1],dup2(g1p.y),b1.y);
            }
            float pw[4] = {0,0,0,0};
#pragma unroll
            for (int i = 0; i < 2; i++){
                float nlr = -sLr[ro+r0+i];
                float ws = sWs[ro+r0+i];
                float2 p = unp(acc[i][0]), qq = unp(acc[i][1]);
                float g[4] = {p.x,p.y,qq.x,qq.y};
#pragma unroll
                for (int j = 0; j < 4; j++){
                    float z = z1r[i][j];
                    float sg = sigmf(z);
                    pw[j] += ws * (nlr*g[j]*(sg*(1.0f + z*(1.0f - sg))));
                }
            }
            *(float4*)&pW1[rg*128+c0] = make_float4(pw[0],pw[1],pw[2],pw[3]);
        }
        __syncthreads();

        // ---- R1 ----
        if (t < 384){
            float s = 0.0f;
            if (t < 128){
#pragma unroll
                for (int g = 0; g < 16; g++) s += pXm[g*128+t];
            } else if (t < 192){
                int d = t-128;
#pragma unroll
                for (int g = 0; g < 4; g++) s += pKm[g*64+d];
            } else if (t < 320){
                int c = t-192;
#pragma unroll
                for (int g = 0; g < 16; g++) s += pW1[g*128+c];
            } else {
                int d = t-320;
#pragma unroll
                for (int g = 0; g < 16; g++) s += pW2[g*64+d];
            }
            exch[par*384 + t] = s;
        }
        asm volatile("barrier.cluster.arrive.aligned;" ::: "memory");
        asm volatile("barrier.cluster.wait.aligned;" ::: "memory");

        // ---- R2 ----
        if (t < 384){
            float ov = exch[par*384 + t];
            float pv = ld_peer(exc_base + (uint32_t)(par*384 + t)*4u, prank);
            float v0 = (rank == 0) ? ov : pv;
            float v1 = (rank == 0) ? pv : ov;
            float total = v0 + v1;
            float m0 = lw[192], m1 = lw[193];
            if (t < 128)       sXm[t]      = m0*sXm[t]      + total;
            else if (t < 192)  sKm[t-128]  = m0*sKm[t-128]  + total;
            else if (t < 320)  sW1s[t-192] = m1*sW1s[t-192] + total;
            else               sW2s[t-320] = m1*sW2s[t-320] + total;
        }
        __syncthreads();

        // ---- FIX: Zq = mp*ZqO + (qc.Km)*W1s ; sq -> sX1 ; dotx ----
        float dx0 = 0.0f, dx1 = 0.0f;
        {
            float mp = lw[192];
            float dq0 = qcb[r0*68+l2]*sKm[l2] + qcb[r0*68+l2+1]*sKm[l2+1];
            float dq1 = qcb[(r0+1)*68+l2]*sKm[l2] + qcb[(r0+1)*68+l2+1]*sKm[l2+1];
#pragma unroll
            for (int o = 16; o > 0; o >>= 1){
                dq0 += __shfl_xor_sync(0xffffffffu, dq0, o);
                dq1 += __shfl_xor_sync(0xffffffffu, dq1, o);
            }
            float4 w1sv = *(const float4*)&sW1s[c0];
            float4 xmv  = *(const float4*)&sXm[c0];
#pragma unroll
            for (int i = 0; i < 2; i++){
                float dq = i ? dq1 : dq0;
                float sq[4]; float dx = 0.0f;
#pragma unroll
                for (int j = 0; j < 4; j++){
                    float z = mp*zqo[i][j] + dq*((const float*)&w1sv)[j];
                    float s = z*sigmf(z);
                    sq[j] = s;
                    dx += s*((const float*)&xmv)[j];
                }
                *(float4*)&sX1[(r0+i)*132+c0] = make_float4(sq[0],sq[1],sq[2],sq[3]);
                if (i) dx1 = dx; else dx0 = dx;
            }
#pragma unroll
            for (int o = 16; o > 0; o >>= 1){
                dx0 += __shfl_xor_sync(0xffffffffu, dx0, o);
                dx1 += __shfl_xor_sync(0xffffffffu, dx1, o);
            }
        }
        __syncwarp();

        // ---- I: y = mp*(sq@W2_old) + dotx*W2s -> sG ----
        {
            float mp = lw[192];
            ull acc[2] = {};
            for (int cc = 0; cc < DMM; cc += 4){
                float4 a0 = *(const float4*)&sX1[(r0+0)*132+cc];
                float4 a1 = *(const float4*)&sX1[(r0+1)*132+cc];
#pragma unroll
                for (int u = 0; u < 4; u++){
                    ull bv = *(const ull*)&sW2[(cc+u)*68+c2];
                    float e0 = u==0?a0.x:u==1?a0.y:u==2?a0.z:a0.w;
                    float e1 = u==0?a1.x:u==1?a1.y:u==2?a1.z:a1.w;
                    FMA2(acc[0],dup2(e0),bv); FMA2(acc[1],dup2(e1),bv);
                }
            }
            float w2s0 = sW2s[c2], w2s1 = sW2s[c2+1];
#pragma unroll
            for (int i = 0; i < 2; i++){
                float dx = i ? dx1 : dx0;
                float2 p = unp(acc[i]);
                *(float2*)&sG[(r0+i)*68+c2] =
                    make_float2(mp*p.x + dx*w2s0, mp*p.y + dx*w2s1);
            }
        }
        __syncthreads();

        // ---- store + tail: prefetch, W updates ----
        for (int e = t; e < 32*64; e += 512){
            int d = e>>5, i = e&31;
            out[(size_t)b*LL*HIDN + ((size_t)(h*DD+d))*LL + (l0+ro+i)] = sG[i*68+d];
        }
        if (ch+1 < NCH) PF(ch+1);
        {
            float mp = lw[192];
            for (int e = t; e < DD*DMM; e += 512){
                int d = e>>7, c = e&127;
                sW1[d*132+c] = mp*sW1[d*132+c] + sKm[d]*sW1s[c];
            }
            for (int e = t; e < DMM*DD; e += 512){
                int c = e>>6, d = e&63;
                float v = mp*sW2[c*68+d] + sXm[c]*sW2s[d];
                sW2[c*68+d] = v; sW2T[d*132+c] = v;
            }
        }
        CPW(0);
        __syncthreads();
    }
#undef PF
}

// ---------------- launch (multi-stream fork/join) ----------------
extern "C" void kernel_launch(void* const* d_in, const int* in_sizes, int n_in,
                              void* d_out, int out_size) {
    (void)in_sizes; (void)n_in; (void)out_size;
    const float* X   = (const float*)d_in[0];
    const float* Wq  = (const float*)d_in[1];
    const float* Wk  = (const float*)d_in[2];
    const float* Wv  = (const float*)d_in[3];
    const float* cqw = (const float*)d_in[4];
    const float* cqb = (const float*)d_in[5];
    const float* ckw = (const float*)d_in[6];
    const float* ckb = (const float*)d_in[7];
    const float* cvw = (const float*)d_in[8];
    const float* cvb = (const float*)d_in[9];
    const float* qnw = (const float*)d_in[10];
    const float* knw = (const float*)d_in[11];
    const float* mdw = (const float*)d_in[12];
    const float* mdb = (const float*)d_in[13];
    const float* sw  = (const float*)d_in[14];
    const float* sb  = (const float*)d_in[15];
    const float* lw  = (const float*)d_in[16];
    const float* lb  = (const float*)d_in[17];
    const float* W1g = (const float*)d_in[18];
    const float* W2g = (const float*)d_in[19];
    float* out = (float*)d_out;

    static cudaStream_t s_aux = nullptr;
    static cudaEvent_t e_fork = nullptr, e_join = nullptr;
    if (!s_aux){
        cudaStreamCreateWithFlags(&s_aux, cudaStreamNonBlocking);
        cudaEventCreateWithFlags(&e_fork, cudaEventDisableTiming);
        cudaEventCreateWithFlags(&e_join, cudaEventDisableTiming);
        cudaFuncSetAttribute(k_qkv, cudaFuncAttributeMaxDynamicSharedMemorySize, QSMEM);
        cudaFuncSetAttribute(k_scan, cudaFuncAttributeMaxDynamicSharedMemorySize, SCAN_BYTES);
    }

    __half *xhi, *whi;
    cudaGetSymbolAddress((void**)&xhi, g_Xhi);
    cudaGetSymbolAddress((void**)&whi, g_Whi);

    cudaEventRecord(e_fork, 0);
    cudaStreamWaitEvent(s_aux, e_fork, 0);
    k_gate<<<dim3(MM/64), 256, 0, s_aux>>>(X, mdw, mdb, sw, sb, lw, lb);
    cudaEventRecord(e_join, s_aux);

    k_cvtX<<<MM*HIDN/1024, 256>>>(X, xhi, MM*HIDN);
    k_cvtW3<<<dim3(HIDN*HIDN/1024, 3), 256>>>(Wq, Wk, Wv, whi);
    k_qkv<<<dim3(HIDN/128, MM/128, 3), 256, QSMEM>>>();
    k_conv<<<dim3(LL/CT, BB, 3), 256>>>(cqw, cqb, ckw, ckb, cvw, cvb, qnw, knw);
    cudaStreamWaitEvent(0, e_join, 0);
    k_scan<<<dim3(BB*HH*2), 512, SCAN_BYTES>>>(W1g, W2g, out);
}